// round 7
// baseline (speedup 1.0000x reference)
#include <cuda_runtime.h>
#include <cuda_fp16.h>
#include <cstdint>
#include <cstddef>

// ---------------------------------------------------------------------------
// Problem constants: B=4, T=2048, C=2048, H=16, S=128 ; M = B*T = 8192
// ---------------------------------------------------------------------------
#define MDIM 8192
#define CD   2048
#define HH   16
#define SSZ  128
#define TTL  2048
#define PCH  32
#define LCH  64

// Scratch (allocation-free: __device__ globals)
__device__ __half g_xp  [(size_t)MDIM * CD];      // x fp16
__device__ __half g_wkvr[(size_t)3 * CD * CD];    // concat(Wk,Wv,Wr) fp16
__device__ __half g_wop [(size_t)CD * CD];        // Wo fp16
__device__ __half g_gp  [(size_t)MDIM * CD];      // gated output fp16
__device__ float  g_k   [(size_t)MDIM * CD];
__device__ float  g_v   [(size_t)MDIM * CD];
__device__ float  g_r   [(size_t)MDIM * CD];
__device__ float  g_stn [4 * HH * PCH * SSZ];     // chunk states: num
__device__ float  g_std [4 * HH * PCH * SSZ];     // chunk states: den

// ---------------------------------------------------------------------------
// helpers
// ---------------------------------------------------------------------------
__device__ __forceinline__ uint32_t smem_u32(const void* p) {
    uint32_t a;
    asm("{ .reg .u64 t; cvta.to.shared.u64 t, %1; cvt.u32.u64 %0, t; }"
        : "=r"(a) : "l"(p));
    return a;
}
__device__ __forceinline__ void cp16(uint32_t dst, const void* src) {
    asm volatile("cp.async.cg.shared.global [%0], [%1], 16;"
                 :: "r"(dst), "l"(src) : "memory");
}
#define CP_COMMIT() asm volatile("cp.async.commit_group;" ::: "memory")
#define CP_WAIT(n)  asm volatile("cp.async.wait_group %0;" :: "n"(n) : "memory")

#define LDSM4(r0, r1, r2, r3, addr)                                        \
    asm volatile("ldmatrix.sync.aligned.m8n8.x4.shared.b16 "               \
                 "{%0,%1,%2,%3}, [%4];"                                    \
                 : "=r"(r0), "=r"(r1), "=r"(r2), "=r"(r3) : "r"(addr))

#define MMA_F16(d, a, b)                                                   \
    asm volatile(                                                          \
        "mma.sync.aligned.m16n8k16.row.col.f32.f16.f16.f32 "               \
        "{%0,%1,%2,%3}, {%4,%5,%6,%7}, {%8,%9}, {%0,%1,%2,%3};"            \
        : "+f"(d[0]), "+f"(d[1]), "+f"(d[2]), "+f"(d[3])                   \
        : "r"(a[0]), "r"(a[1]), "r"(a[2]), "r"(a[3]), "r"(b[0]), "r"(b[1]))

// ---------------------------------------------------------------------------
// pack-all: x + 4 weights -> fp16, one launch
// ---------------------------------------------------------------------------
#define NX4 ((long)MDIM * CD / 4)
#define NW4 ((long)CD * CD / 4)

__global__ __launch_bounds__(256) void pack_all(
    const float* __restrict__ x,  const float* __restrict__ Wk,
    const float* __restrict__ Wv, const float* __restrict__ Wr,
    const float* __restrict__ Wo,
    __half* __restrict__ xp, __half* __restrict__ wkvr, __half* __restrict__ wop)
{
    long i = (long)blockIdx.x * blockDim.x + threadIdx.x;
    const float* src;
    __half* dst;
    long j;
    if (i < NX4) {
        src = x; dst = xp; j = i;
    } else {
        long i2 = i - NX4;
        int  w  = (int)(i2 / NW4);
        j = i2 - (long)w * NW4;
        if      (w == 0) { src = Wk; dst = wkvr; }
        else if (w == 1) { src = Wv; dst = wkvr + (size_t)CD * CD; }
        else if (w == 2) { src = Wr; dst = wkvr + (size_t)2 * CD * CD; }
        else             { src = Wo; dst = wop; }
    }
    float4 f = ((const float4*)src)[j];
    __half2* d = (__half2*)dst + 2 * j;
    d[0] = __floats2half2_rn(f.x, f.y);
    d[1] = __floats2half2_rn(f.z, f.w);
}

// ---------------------------------------------------------------------------
// FP16 tensor GEMM: C[M,N] = A[M,K] @ B[N,K]^T, fp16 in, f32 out.
// Block 128x128x32, 256 thr = 8 warps (2M x 4N). 3-stage cp.async pipeline,
// one __syncthreads per iter; prefetch issued immediately after the barrier;
// B fragments for both k16 sub-steps hoisted before compute.
// ---------------------------------------------------------------------------
#define LDH 40
#define BUFB (128 * LDH * 2)
#define SMEM_GEMM (6 * BUFB)

__global__ __launch_bounds__(256, 2) void gemm_nt_h(
    const __half* __restrict__ A, const __half* __restrict__ B,
    float* __restrict__ C0, float* __restrict__ C1, float* __restrict__ C2,
    int K, int nsplit)
{
    extern __shared__ __align__(16) char dyn_smem[];
    const uint32_t sA = smem_u32(dyn_smem);
    const uint32_t sB = sA + 3 * BUFB;

    const int tid  = threadIdx.x;
    const int lane = tid & 31;
    const int wid  = tid >> 5;
    const int wm   = (wid & 1) * 64;
    const int wn   = (wid >> 1) * 32;
    const int g    = lane >> 2;
    const int t4   = lane & 3;

    const int lr = tid >> 2;
    const int lu = tid & 3;
    const __half* Ap0 = A + (size_t)(blockIdx.y * 128 + lr) * K + lu * 8;
    const __half* Ap1 = Ap0 + (size_t)64 * K;
    const __half* Bp0 = B + (size_t)(blockIdx.x * 128 + lr) * K + lu * 8;
    const __half* Bp1 = Bp0 + (size_t)64 * K;
    const uint32_t da0 = sA + lr * 80 + lu * 16, da1 = da0 + 64 * 80;
    const uint32_t db0 = sB + lr * 80 + lu * 16, db1 = db0 + 64 * 80;

    const uint32_t a_base = sA + ((wm + (lane & 15)) * LDH + ((lane >> 4) << 3)) * 2;
    const uint32_t b_base = sB + ((wn + (lane & 7) + ((lane >> 4) & 1) * 8) * LDH
                                  + (((lane >> 3) & 1) << 3)) * 2;

    float acc[4][4][4];
#pragma unroll
    for (int mi = 0; mi < 4; mi++)
#pragma unroll
        for (int ni = 0; ni < 4; ni++)
#pragma unroll
            for (int j = 0; j < 4; j++) acc[mi][ni][j] = 0.f;

    const int KT = K / 32;   // 64

#pragma unroll
    for (int pf = 0; pf < 2; pf++) {
        const uint32_t o = (uint32_t)(pf * BUFB);
        const int koff = pf * 32;
        cp16(da0 + o, Ap0 + koff); cp16(da1 + o, Ap1 + koff);
        cp16(db0 + o, Bp0 + koff); cp16(db1 + o, Bp1 + koff);
        CP_COMMIT();
    }

    int st = 0;
    for (int kt = 0; kt < KT; kt++) {
        if (kt + 1 < KT) { CP_WAIT(1); } else { CP_WAIT(0); }
        __syncthreads();

        // issue next prefetch FIRST (stage kt-1 is free after the barrier)
        if (kt + 2 < KT) {
            const int ns = (st + 2 > 2) ? (st - 1) : (st + 2);
            const uint32_t o = (uint32_t)(ns * BUFB);
            const int koff = (kt + 2) * 32;
            cp16(da0 + o, Ap0 + koff); cp16(da1 + o, Ap1 + koff);
            cp16(db0 + o, Bp0 + koff); cp16(db1 + o, Bp1 + koff);
            CP_COMMIT();
        }

        const uint32_t so = (uint32_t)(st * BUFB);

        // hoist B fragments for both k16 sub-steps
        uint32_t bf[2][4][2];
#pragma unroll
        for (int ks = 0; ks < 2; ks++)
#pragma unroll
            for (int pr = 0; pr < 2; pr++)
                LDSM4(bf[ks][2 * pr][0], bf[ks][2 * pr][1],
                      bf[ks][2 * pr + 1][0], bf[ks][2 * pr + 1][1],
                      b_base + so + pr * (16 * 80) + ks * 32);

#pragma unroll
        for (int ks = 0; ks < 2; ks++) {
            uint32_t af[4][4];
#pragma unroll
            for (int mi = 0; mi < 4; mi++)
                LDSM4(af[mi][0], af[mi][1], af[mi][2], af[mi][3],
                      a_base + so + mi * (16 * 80) + ks * 32);
#pragma unroll
            for (int mi = 0; mi < 4; mi++)
#pragma unroll
                for (int ni = 0; ni < 4; ni++)
                    MMA_F16(acc[mi][ni], af[mi], bf[ks][ni]);
        }
        st = (st + 1 > 2) ? 0 : (st + 1);
    }

    float* C = C0;
    int cbx = blockIdx.x;
    if (nsplit > 0) {
        const int which = blockIdx.x / nsplit;
        C = (which == 0) ? C0 : ((which == 1) ? C1 : C2);
        cbx = blockIdx.x - which * nsplit;
    }
#pragma unroll
    for (int mi = 0; mi < 4; mi++) {
#pragma unroll
        for (int ni = 0; ni < 4; ni++) {
            const int row = blockIdx.y * 128 + wm + mi * 16 + g;
            const int col = cbx * 128 + wn + ni * 8 + 2 * t4;
            *(float2*)&C[(size_t)row * CD + col] =
                make_float2(acc[mi][ni][0], acc[mi][ni][1]);
            *(float2*)&C[(size_t)(row + 8) * CD + col] =
                make_float2(acc[mi][ni][2], acc[mi][ni][3]);
        }
    }
}

// ---------------------------------------------------------------------------
// WKV chunk-parallel scan, vectorized: 4 channels / thread (float4).
// Block = 128 threads = 512 channels = 4 heads. Grid (PCH, HH/4, B).
// ---------------------------------------------------------------------------
__device__ __forceinline__ float4 ld4(const float* p) { return *(const float4*)p; }

__global__ __launch_bounds__(128) void wkv_p1(
    const float* __restrict__ k, const float* __restrict__ v,
    const float* __restrict__ td, const float* __restrict__ tf)
{
    const int t = threadIdx.x, p = blockIdx.x, hg = blockIdx.y, b = blockIdx.z;
    const int c4 = hg * 512 + t * 4;
    float4 td4 = ld4(td + c4);
    float4 dec = make_float4(expf(-expf(td4.x)), expf(-expf(td4.y)),
                             expf(-expf(td4.z)), expf(-expf(td4.w)));
    size_t base = ((size_t)(b * TTL + p * LCH)) * CD + c4;
    float4 num = make_float4(0.f, 0.f, 0.f, 0.f);
    float4 den = num;
    int i0 = 0;
    if (p == 0) {   // first-token: w scaled by exp(time_first)
        float4 tf4 = ld4(tf + c4);
        float4 kk = ld4(k + base), vv = ld4(v + base);
        float wx = expf(tf4.x) * __expf(fminf(fmaxf(kk.x, -10.f), 10.f));
        float wy = expf(tf4.y) * __expf(fminf(fmaxf(kk.y, -10.f), 10.f));
        float wz = expf(tf4.z) * __expf(fminf(fmaxf(kk.z, -10.f), 10.f));
        float ww = expf(tf4.w) * __expf(fminf(fmaxf(kk.w, -10.f), 10.f));
        num = make_float4(wx * vv.x, wy * vv.y, wz * vv.z, ww * vv.w);
        den = make_float4(wx, wy, wz, ww);
        base += CD; i0 = 1;
    }
#pragma unroll 4
    for (int i = i0; i < LCH; i++) {
        float4 kk = ld4(k + base), vv = ld4(v + base);
        float wx = __expf(fminf(fmaxf(kk.x, -10.f), 10.f));
        float wy = __expf(fminf(fmaxf(kk.y, -10.f), 10.f));
        float wz = __expf(fminf(fmaxf(kk.z, -10.f), 10.f));
        float ww = __expf(fminf(fmaxf(kk.w, -10.f), 10.f));
        num.x = fmaf(dec.x, num.x, wx * vv.x);
        num.y = fmaf(dec.y, num.y, wy * vv.y);
        num.z = fmaf(dec.z, num.z, wz * vv.z);
        num.w = fmaf(dec.w, num.w, ww * vv.w);
        den.x = fmaf(dec.x, den.x, wx);
        den.y = fmaf(dec.y, den.y, wy);
        den.z = fmaf(dec.z, den.z, wz);
        den.w = fmaf(dec.w, den.w, ww);
        base += CD;
    }
    const size_t idx = (((size_t)b * HH + (c4 >> 7)) * PCH + p) * SSZ + (c4 & 127);
    *(float4*)&g_stn[idx] = num;
    *(float4*)&g_std[idx] = den;
}

__global__ __launch_bounds__(128) void wkv_p2(const float* __restrict__ td)
{
    const int s = threadIdx.x, h = blockIdx.x, b = blockIdx.y;
    const float dC = expf(-(float)LCH * expf(td[h * SSZ + s]));
    float rn = 0.f, rd = 0.f;
    size_t base = ((size_t)b * HH + h) * PCH;
    for (int p = 0; p < PCH; p++) {
        size_t idx = (base + p) * SSZ + s;
        float cn = g_stn[idx], cd = g_std[idx];
        g_stn[idx] = rn; g_std[idx] = rd;        // exclusive prefix
        rn = fmaf(dC, rn, cn);
        rd = fmaf(dC, rd, cd);
    }
}

__global__ __launch_bounds__(128) void wkv_p3(
    const float* __restrict__ k, const float* __restrict__ v,
    const float* __restrict__ r,
    const float* __restrict__ td, const float* __restrict__ tf)
{
    const int t = threadIdx.x, p = blockIdx.x, hg = blockIdx.y, b = blockIdx.z;
    const int c4 = hg * 512 + t * 4;
    float4 td4 = ld4(td + c4);
    float4 dec = make_float4(expf(-expf(td4.x)), expf(-expf(td4.y)),
                             expf(-expf(td4.z)), expf(-expf(td4.w)));
    const size_t idx = (((size_t)b * HH + (c4 >> 7)) * PCH + p) * SSZ + (c4 & 127);
    float4 num = *(const float4*)&g_stn[idx];
    float4 den = *(const float4*)&g_std[idx];
    size_t base = ((size_t)(b * TTL + p * LCH)) * CD + c4;

#pragma unroll 4
    for (int i = 0; i < LCH; i++) {
        float4 kk = ld4(k + base), vv = ld4(v + base), rr = ld4(r + base);
        float wx = __expf(fminf(fmaxf(kk.x, -10.f), 10.f));
        float wy = __expf(fminf(fmaxf(kk.y, -10.f), 10.f));
        float wz = __expf(fminf(fmaxf(kk.z, -10.f), 10.f));
        float ww = __expf(fminf(fmaxf(kk.w, -10.f), 10.f));
        if (p == 0 && i == 0) {
            float4 tf4 = ld4(tf + c4);
            wx *= expf(tf4.x); wy *= expf(tf4.y);
            wz *= expf(tf4.z); ww *= expf(tf4.w);
        }
        num.x = fmaf(dec.x, num.x, wx * vv.x);
        num.y = fmaf(dec.y, num.y, wy * vv.y);
        num.z = fmaf(dec.z, num.z, wz * vv.z);
        num.w = fmaf(dec.w, num.w, ww * vv.w);
        den.x = fmaf(dec.x, den.x, wx);
        den.y = fmaf(dec.y, den.y, wy);
        den.z = fmaf(dec.z, den.z, wz);
        den.w = fmaf(dec.w, den.w, ww);
        float ox = (num.x / (den.x + 1e-6f)) / (1.f + __expf(-rr.x));
        float oy = (num.y / (den.y + 1e-6f)) / (1.f + __expf(-rr.y));
        float oz = (num.z / (den.z + 1e-6f)) / (1.f + __expf(-rr.z));
        float ow = (num.w / (den.w + 1e-6f)) / (1.f + __expf(-rr.w));
        __half2* dst = (__half2*)&g_gp[base];
        dst[0] = __floats2half2_rn(ox, oy);
        dst[1] = __floats2half2_rn(oz, ow);
        base += CD;
    }
}

// ---------------------------------------------------------------------------
extern "C" void kernel_launch(void* const* d_in, const int* in_sizes, int n_in,
                              void* d_out, int out_size)
{
    const float* x  = (const float*)d_in[0];
    const float* Wk = (const float*)d_in[1];
    const float* Wv = (const float*)d_in[2];
    const float* Wr = (const float*)d_in[3];
    const float* Wo = (const float*)d_in[4];
    const float* td = (const float*)d_in[5];
    const float* tf = (const float*)d_in[6];
    float* out = (float*)d_out;

    __half *xp, *wkvr, *wop, *gp;
    float *pk, *pv, *pr;
    cudaGetSymbolAddress((void**)&xp,   g_xp);
    cudaGetSymbolAddress((void**)&wkvr, g_wkvr);
    cudaGetSymbolAddress((void**)&wop,  g_wop);
    cudaGetSymbolAddress((void**)&gp,   g_gp);
    cudaGetSymbolAddress((void**)&pk,   g_k);
    cudaGetSymbolAddress((void**)&pv,   g_v);
    cudaGetSymbolAddress((void**)&pr,   g_r);

    cudaFuncSetAttribute(gemm_nt_h, cudaFuncAttributeMaxDynamicSharedMemorySize,
                         SMEM_GEMM);

    const long nAll = NX4 + 4 * NW4;
    pack_all<<<(unsigned)((nAll + 255) / 256), 256>>>(
        x, Wk, Wv, Wr, Wo, xp, wkvr, wop);

    dim3 gridF(3 * CD / 128, MDIM / 128);   // (48, 64)
    gemm_nt_h<<<gridF, 256, SMEM_GEMM>>>(xp, wkvr, pk, pv, pr, CD, CD / 128);

    wkv_p1<<<dim3(PCH, HH / 4, 4), 128>>>(pk, pv, td, tf);
    wkv_p2<<<dim3(HH, 4), 128>>>(td);
    wkv_p3<<<dim3(PCH, HH / 4, 4), 128>>>(pk, pv, pr, td, tf);

    dim3 gridO(CD / 128, MDIM / 128);       // (16, 64)
    gemm_nt_h<<<gridO, 256, SMEM_GEMM>>>(gp, wop, out, nullptr, nullptr, CD, 0);
}

// round 8
// speedup vs baseline: 1.1165x; 1.1165x over previous
#include <cuda_runtime.h>
#include <cuda_fp16.h>
#include <cstdint>
#include <cstddef>

// ---------------------------------------------------------------------------
// Problem constants: B=4, T=2048, C=2048, H=16, S=128 ; M = B*T = 8192
// ---------------------------------------------------------------------------
#define MDIM 8192
#define CD   2048
#define HH   16
#define SSZ  128
#define TTL  2048
#define PCH  32
#define LCH  64

// Scratch (allocation-free: __device__ globals)
__device__ __half g_xp  [(size_t)MDIM * CD];      // x fp16
__device__ __half g_wkvr[(size_t)3 * CD * CD];    // concat(Wk,Wv,Wr) fp16
__device__ __half g_wop [(size_t)CD * CD];        // Wo fp16
__device__ __half g_gp  [(size_t)MDIM * CD];      // gated output fp16
__device__ float  g_k   [(size_t)MDIM * CD];
__device__ float  g_v   [(size_t)MDIM * CD];
__device__ float  g_r   [(size_t)MDIM * CD];
__device__ float  g_stn [4 * HH * PCH * SSZ];     // chunk states: num
__device__ float  g_std [4 * HH * PCH * SSZ];     // chunk states: den

// ---------------------------------------------------------------------------
// helpers
// ---------------------------------------------------------------------------
__device__ __forceinline__ uint32_t smem_u32(const void* p) {
    uint32_t a;
    asm("{ .reg .u64 t; cvta.to.shared.u64 t, %1; cvt.u32.u64 %0, t; }"
        : "=r"(a) : "l"(p));
    return a;
}
__device__ __forceinline__ void cp16(uint32_t dst, const void* src) {
    asm volatile("cp.async.cg.shared.global [%0], [%1], 16;"
                 :: "r"(dst), "l"(src) : "memory");
}
#define CP_COMMIT() asm volatile("cp.async.commit_group;" ::: "memory")
#define CP_WAIT(n)  asm volatile("cp.async.wait_group %0;" :: "n"(n) : "memory")

#define LDSM4(r0, r1, r2, r3, addr)                                        \
    asm volatile("ldmatrix.sync.aligned.m8n8.x4.shared.b16 "               \
                 "{%0,%1,%2,%3}, [%4];"                                    \
                 : "=r"(r0), "=r"(r1), "=r"(r2), "=r"(r3) : "r"(addr))

#define MMA_F16(d, a, b)                                                   \
    asm volatile(                                                          \
        "mma.sync.aligned.m16n8k16.row.col.f32.f16.f16.f32 "               \
        "{%0,%1,%2,%3}, {%4,%5,%6,%7}, {%8,%9}, {%0,%1,%2,%3};"            \
        : "+f"(d[0]), "+f"(d[1]), "+f"(d[2]), "+f"(d[3])                   \
        : "r"(a[0]), "r"(a[1]), "r"(a[2]), "r"(a[3]), "r"(b[0]), "r"(b[1]))

// ---------------------------------------------------------------------------
// pack-all: x + 4 weights -> fp16, one launch
// ---------------------------------------------------------------------------
#define NX4 ((long)MDIM * CD / 4)
#define NW4 ((long)CD * CD / 4)

__global__ __launch_bounds__(256) void pack_all(
    const float* __restrict__ x,  const float* __restrict__ Wk,
    const float* __restrict__ Wv, const float* __restrict__ Wr,
    const float* __restrict__ Wo,
    __half* __restrict__ xp, __half* __restrict__ wkvr, __half* __restrict__ wop)
{
    long i = (long)blockIdx.x * blockDim.x + threadIdx.x;
    const float* src;
    __half* dst;
    long j;
    if (i < NX4) {
        src = x; dst = xp; j = i;
    } else {
        long i2 = i - NX4;
        int  w  = (int)(i2 / NW4);
        j = i2 - (long)w * NW4;
        if      (w == 0) { src = Wk; dst = wkvr; }
        else if (w == 1) { src = Wv; dst = wkvr + (size_t)CD * CD; }
        else if (w == 2) { src = Wr; dst = wkvr + (size_t)2 * CD * CD; }
        else             { src = Wo; dst = wop; }
    }
    float4 f = ((const float4*)src)[j];
    __half2* d = (__half2*)dst + 2 * j;
    d[0] = __floats2half2_rn(f.x, f.y);
    d[1] = __floats2half2_rn(f.z, f.w);
}

// ---------------------------------------------------------------------------
// FP16 tensor GEMM (R6-proven schedule): C[M,N] = A[M,K] @ B[N,K]^T.
// Block 128x128x32, 256 thr = 8 warps (2M x 4N). 3-stage cp.async pipeline,
// one __syncthreads per iter; per-ks interleaved LDSM; prefetch after compute.
// ---------------------------------------------------------------------------
#define LDH 40
#define BUFB (128 * LDH * 2)
#define SMEM_GEMM (6 * BUFB)

__global__ __launch_bounds__(256, 2) void gemm_nt_h(
    const __half* __restrict__ A, const __half* __restrict__ B,
    float* __restrict__ C0, float* __restrict__ C1, float* __restrict__ C2,
    int K, int nsplit)
{
    extern __shared__ __align__(16) char dyn_smem[];
    const uint32_t sA = smem_u32(dyn_smem);
    const uint32_t sB = sA + 3 * BUFB;

    const int tid  = threadIdx.x;
    const int lane = tid & 31;
    const int wid  = tid >> 5;
    const int wm   = (wid & 1) * 64;
    const int wn   = (wid >> 1) * 32;
    const int g    = lane >> 2;
    const int t4   = lane & 3;

    const int lr = tid >> 2;
    const int lu = tid & 3;
    const __half* Ap0 = A + (size_t)(blockIdx.y * 128 + lr) * K + lu * 8;
    const __half* Ap1 = Ap0 + (size_t)64 * K;
    const __half* Bp0 = B + (size_t)(blockIdx.x * 128 + lr) * K + lu * 8;
    const __half* Bp1 = Bp0 + (size_t)64 * K;
    const uint32_t da0 = sA + lr * 80 + lu * 16, da1 = da0 + 64 * 80;
    const uint32_t db0 = sB + lr * 80 + lu * 16, db1 = db0 + 64 * 80;

    const uint32_t a_base = sA + ((wm + (lane & 15)) * LDH + ((lane >> 4) << 3)) * 2;
    const uint32_t b_base = sB + ((wn + (lane & 7) + ((lane >> 4) & 1) * 8) * LDH
                                  + (((lane >> 3) & 1) << 3)) * 2;

    float acc[4][4][4];
#pragma unroll
    for (int mi = 0; mi < 4; mi++)
#pragma unroll
        for (int ni = 0; ni < 4; ni++)
#pragma unroll
            for (int j = 0; j < 4; j++) acc[mi][ni][j] = 0.f;

    const int KT = K / 32;   // 64

#pragma unroll
    for (int pf = 0; pf < 2; pf++) {
        const uint32_t o = (uint32_t)(pf * BUFB);
        const int koff = pf * 32;
        cp16(da0 + o, Ap0 + koff); cp16(da1 + o, Ap1 + koff);
        cp16(db0 + o, Bp0 + koff); cp16(db1 + o, Bp1 + koff);
        CP_COMMIT();
    }

    int st = 0;
    for (int kt = 0; kt < KT; kt++) {
        if (kt + 1 < KT) { CP_WAIT(1); } else { CP_WAIT(0); }
        __syncthreads();

        const uint32_t so = (uint32_t)(st * BUFB);
#pragma unroll
        for (int ks = 0; ks < 2; ks++) {
            const uint32_t ko = ks * 32;
            uint32_t af[4][4];
            uint32_t bf[4][2];
#pragma unroll
            for (int mi = 0; mi < 4; mi++)
                LDSM4(af[mi][0], af[mi][1], af[mi][2], af[mi][3],
                      a_base + so + mi * (16 * 80) + ko);
#pragma unroll
            for (int pr = 0; pr < 2; pr++)
                LDSM4(bf[2 * pr][0], bf[2 * pr][1], bf[2 * pr + 1][0], bf[2 * pr + 1][1],
                      b_base + so + pr * (16 * 80) + ko);
#pragma unroll
            for (int mi = 0; mi < 4; mi++)
#pragma unroll
                for (int ni = 0; ni < 4; ni++)
                    MMA_F16(acc[mi][ni], af[mi], bf[ni]);
        }

        if (kt + 2 < KT) {
            const int ns = (st + 2 > 2) ? (st - 1) : (st + 2);
            const uint32_t o = (uint32_t)(ns * BUFB);
            const int koff = (kt + 2) * 32;
            cp16(da0 + o, Ap0 + koff); cp16(da1 + o, Ap1 + koff);
            cp16(db0 + o, Bp0 + koff); cp16(db1 + o, Bp1 + koff);
            CP_COMMIT();
        }
        st = (st + 1 > 2) ? 0 : (st + 1);
    }

    float* C = C0;
    int cbx = blockIdx.x;
    if (nsplit > 0) {
        const int which = blockIdx.x / nsplit;
        C = (which == 0) ? C0 : ((which == 1) ? C1 : C2);
        cbx = blockIdx.x - which * nsplit;
    }
#pragma unroll
    for (int mi = 0; mi < 4; mi++) {
#pragma unroll
        for (int ni = 0; ni < 4; ni++) {
            const int row = blockIdx.y * 128 + wm + mi * 16 + g;
            const int col = cbx * 128 + wn + ni * 8 + 2 * t4;
            *(float2*)&C[(size_t)row * CD + col] =
                make_float2(acc[mi][ni][0], acc[mi][ni][1]);
            *(float2*)&C[(size_t)(row + 8) * CD + col] =
                make_float2(acc[mi][ni][2], acc[mi][ni][3]);
        }
    }
}

// ---------------------------------------------------------------------------
// WKV chunk-parallel scan, vectorized: 4 channels / thread (float4).
// p1/p3: block = 128 threads = 512 channels = 4 heads; grid (PCH, HH/4, B).
// p2: same channel vectorization; grid (HH/4, B).
// ---------------------------------------------------------------------------
__device__ __forceinline__ float4 ld4(const float* p) { return *(const float4*)p; }

__global__ __launch_bounds__(128) void wkv_p1(
    const float* __restrict__ k, const float* __restrict__ v,
    const float* __restrict__ td, const float* __restrict__ tf)
{
    const int t = threadIdx.x, p = blockIdx.x, hg = blockIdx.y, b = blockIdx.z;
    const int c4 = hg * 512 + t * 4;
    float4 td4 = ld4(td + c4);
    float4 dec = make_float4(expf(-expf(td4.x)), expf(-expf(td4.y)),
                             expf(-expf(td4.z)), expf(-expf(td4.w)));
    size_t base = ((size_t)(b * TTL + p * LCH)) * CD + c4;
    float4 num = make_float4(0.f, 0.f, 0.f, 0.f);
    float4 den = num;
    int i0 = 0;
    if (p == 0) {
        float4 tf4 = ld4(tf + c4);
        float4 kk = ld4(k + base), vv = ld4(v + base);
        float wx = expf(tf4.x) * __expf(fminf(fmaxf(kk.x, -10.f), 10.f));
        float wy = expf(tf4.y) * __expf(fminf(fmaxf(kk.y, -10.f), 10.f));
        float wz = expf(tf4.z) * __expf(fminf(fmaxf(kk.z, -10.f), 10.f));
        float ww = expf(tf4.w) * __expf(fminf(fmaxf(kk.w, -10.f), 10.f));
        num = make_float4(wx * vv.x, wy * vv.y, wz * vv.z, ww * vv.w);
        den = make_float4(wx, wy, wz, ww);
        base += CD; i0 = 1;
    }
#pragma unroll 4
    for (int i = i0; i < LCH; i++) {
        float4 kk = ld4(k + base), vv = ld4(v + base);
        float wx = __expf(fminf(fmaxf(kk.x, -10.f), 10.f));
        float wy = __expf(fminf(fmaxf(kk.y, -10.f), 10.f));
        float wz = __expf(fminf(fmaxf(kk.z, -10.f), 10.f));
        float ww = __expf(fminf(fmaxf(kk.w, -10.f), 10.f));
        num.x = fmaf(dec.x, num.x, wx * vv.x);
        num.y = fmaf(dec.y, num.y, wy * vv.y);
        num.z = fmaf(dec.z, num.z, wz * vv.z);
        num.w = fmaf(dec.w, num.w, ww * vv.w);
        den.x = fmaf(dec.x, den.x, wx);
        den.y = fmaf(dec.y, den.y, wy);
        den.z = fmaf(dec.z, den.z, wz);
        den.w = fmaf(dec.w, den.w, ww);
        base += CD;
    }
    const size_t idx = (((size_t)b * HH + (c4 >> 7)) * PCH + p) * SSZ + (c4 & 127);
    *(float4*)&g_stn[idx] = num;
    *(float4*)&g_std[idx] = den;
}

__global__ __launch_bounds__(128) void wkv_p2(const float* __restrict__ td)
{
    const int t = threadIdx.x, hg = blockIdx.x, b = blockIdx.y;
    const int c4 = hg * 512 + t * 4;
    const int h  = c4 >> 7;
    const int s4 = c4 & 127;
    float4 td4 = ld4(td + c4);
    float4 dC = make_float4(expf(-(float)LCH * expf(td4.x)),
                            expf(-(float)LCH * expf(td4.y)),
                            expf(-(float)LCH * expf(td4.z)),
                            expf(-(float)LCH * expf(td4.w)));
    float4 rn = make_float4(0.f, 0.f, 0.f, 0.f);
    float4 rd = rn;
    size_t base = ((size_t)b * HH + h) * PCH;
    for (int p = 0; p < PCH; p++) {
        size_t idx = (base + p) * SSZ + s4;
        float4 cn = *(const float4*)&g_stn[idx];
        float4 cd = *(const float4*)&g_std[idx];
        *(float4*)&g_stn[idx] = rn;
        *(float4*)&g_std[idx] = rd;
        rn.x = fmaf(dC.x, rn.x, cn.x); rn.y = fmaf(dC.y, rn.y, cn.y);
        rn.z = fmaf(dC.z, rn.z, cn.z); rn.w = fmaf(dC.w, rn.w, cn.w);
        rd.x = fmaf(dC.x, rd.x, cd.x); rd.y = fmaf(dC.y, rd.y, cd.y);
        rd.z = fmaf(dC.z, rd.z, cd.z); rd.w = fmaf(dC.w, rd.w, cd.w);
    }
}

__global__ __launch_bounds__(128) void wkv_p3(
    const float* __restrict__ k, const float* __restrict__ v,
    const float* __restrict__ r,
    const float* __restrict__ td, const float* __restrict__ tf)
{
    const int t = threadIdx.x, p = blockIdx.x, hg = blockIdx.y, b = blockIdx.z;
    const int c4 = hg * 512 + t * 4;
    float4 td4 = ld4(td + c4);
    float4 dec = make_float4(expf(-expf(td4.x)), expf(-expf(td4.y)),
                             expf(-expf(td4.z)), expf(-expf(td4.w)));
    const size_t idx = (((size_t)b * HH + (c4 >> 7)) * PCH + p) * SSZ + (c4 & 127);
    float4 num = *(const float4*)&g_stn[idx];
    float4 den = *(const float4*)&g_std[idx];
    size_t base = ((size_t)(b * TTL + p * LCH)) * CD + c4;

#pragma unroll 4
    for (int i = 0; i < LCH; i++) {
        float4 kk = ld4(k + base), vv = ld4(v + base), rr = ld4(r + base);
        float wx = __expf(fminf(fmaxf(kk.x, -10.f), 10.f));
        float wy = __expf(fminf(fmaxf(kk.y, -10.f), 10.f));
        float wz = __expf(fminf(fmaxf(kk.z, -10.f), 10.f));
        float ww = __expf(fminf(fmaxf(kk.w, -10.f), 10.f));
        if (p == 0 && i == 0) {
            float4 tf4 = ld4(tf + c4);
            wx *= expf(tf4.x); wy *= expf(tf4.y);
            wz *= expf(tf4.z); ww *= expf(tf4.w);
        }
        num.x = fmaf(dec.x, num.x, wx * vv.x);
        num.y = fmaf(dec.y, num.y, wy * vv.y);
        num.z = fmaf(dec.z, num.z, wz * vv.z);
        num.w = fmaf(dec.w, num.w, ww * vv.w);
        den.x = fmaf(dec.x, den.x, wx);
        den.y = fmaf(dec.y, den.y, wy);
        den.z = fmaf(dec.z, den.z, wz);
        den.w = fmaf(dec.w, den.w, ww);
        float ox = (num.x / (den.x + 1e-6f)) / (1.f + __expf(-rr.x));
        float oy = (num.y / (den.y + 1e-6f)) / (1.f + __expf(-rr.y));
        float oz = (num.z / (den.z + 1e-6f)) / (1.f + __expf(-rr.z));
        float ow = (num.w / (den.w + 1e-6f)) / (1.f + __expf(-rr.w));
        __half2* dst = (__half2*)&g_gp[base];
        dst[0] = __floats2half2_rn(ox, oy);
        dst[1] = __floats2half2_rn(oz, ow);
        base += CD;
    }
}

// ---------------------------------------------------------------------------
extern "C" void kernel_launch(void* const* d_in, const int* in_sizes, int n_in,
                              void* d_out, int out_size)
{
    const float* x  = (const float*)d_in[0];
    const float* Wk = (const float*)d_in[1];
    const float* Wv = (const float*)d_in[2];
    const float* Wr = (const float*)d_in[3];
    const float* Wo = (const float*)d_in[4];
    const float* td = (const float*)d_in[5];
    const float* tf = (const float*)d_in[6];
    float* out = (float*)d_out;

    __half *xp, *wkvr, *wop, *gp;
    float *pk, *pv, *pr;
    cudaGetSymbolAddress((void**)&xp,   g_xp);
    cudaGetSymbolAddress((void**)&wkvr, g_wkvr);
    cudaGetSymbolAddress((void**)&wop,  g_wop);
    cudaGetSymbolAddress((void**)&gp,   g_gp);
    cudaGetSymbolAddress((void**)&pk,   g_k);
    cudaGetSymbolAddress((void**)&pv,   g_v);
    cudaGetSymbolAddress((void**)&pr,   g_r);

    cudaFuncSetAttribute(gemm_nt_h, cudaFuncAttributeMaxDynamicSharedMemorySize,
                         SMEM_GEMM);

    const long nAll = NX4 + 4 * NW4;
    pack_all<<<(unsigned)((nAll + 255) / 256), 256>>>(
        x, Wk, Wv, Wr, Wo, xp, wkvr, wop);

    dim3 gridF(3 * CD / 128, MDIM / 128);   // (48, 64)
    gemm_nt_h<<<gridF, 256, SMEM_GEMM>>>(xp, wkvr, pk, pv, pr, CD, CD / 128);

    wkv_p1<<<dim3(PCH, HH / 4, 4), 128>>>(pk, pv, td, tf);
    wkv_p2<<<dim3(HH / 4, 4), 128>>>(td);
    wkv_p3<<<dim3(PCH, HH / 4, 4), 128>>>(pk, pv, pr, td, tf);

    dim3 gridO(CD / 128, MDIM / 128);       // (16, 64)
    gemm_nt_h<<<gridO, 256, SMEM_GEMM>>>(gp, wop, out, nullptr, nullptr, CD, 0);
}

// round 9
// speedup vs baseline: 1.1532x; 1.0329x over previous
#include <cuda_runtime.h>
#include <cuda_fp16.h>
#include <cstdint>
#include <cstddef>

// ---------------------------------------------------------------------------
// Problem constants: B=4, T=2048, C=2048, H=16, S=128 ; M = B*T = 8192
// ---------------------------------------------------------------------------
#define MDIM 8192
#define CD   2048
#define HH   16
#define SSZ  128
#define TTL  2048
#define PCH  32
#define LCH  64

// Scratch (allocation-free: __device__ globals)
__device__ __half g_xp  [(size_t)MDIM * CD];      // x fp16
__device__ __half g_wkvr[(size_t)3 * CD * CD];    // concat(Wk,Wv,Wr) fp16
__device__ __half g_wop [(size_t)CD * CD];        // Wo fp16
__device__ __half g_gp  [(size_t)MDIM * CD];      // gated output fp16
__device__ float  g_k   [(size_t)MDIM * CD];
__device__ float  g_v   [(size_t)MDIM * CD];
__device__ float  g_r   [(size_t)MDIM * CD];
__device__ float2 g_st  [4 * HH * PCH * SSZ];     // chunk states (num,den) AoS

// ---------------------------------------------------------------------------
// helpers
// ---------------------------------------------------------------------------
__device__ __forceinline__ uint32_t smem_u32(const void* p) {
    uint32_t a;
    asm("{ .reg .u64 t; cvta.to.shared.u64 t, %1; cvt.u32.u64 %0, t; }"
        : "=r"(a) : "l"(p));
    return a;
}
__device__ __forceinline__ void cp16(uint32_t dst, const void* src) {
    asm volatile("cp.async.cg.shared.global [%0], [%1], 16;"
                 :: "r"(dst), "l"(src) : "memory");
}
#define CP_COMMIT() asm volatile("cp.async.commit_group;" ::: "memory")
#define CP_WAIT(n)  asm volatile("cp.async.wait_group %0;" :: "n"(n) : "memory")

#define LDSM4(r0, r1, r2, r3, addr)                                        \
    asm volatile("ldmatrix.sync.aligned.m8n8.x4.shared.b16 "               \
                 "{%0,%1,%2,%3}, [%4];"                                    \
                 : "=r"(r0), "=r"(r1), "=r"(r2), "=r"(r3) : "r"(addr))

#define MMA_F16(d, a, b)                                                   \
    asm volatile(                                                          \
        "mma.sync.aligned.m16n8k16.row.col.f32.f16.f16.f32 "               \
        "{%0,%1,%2,%3}, {%4,%5,%6,%7}, {%8,%9}, {%0,%1,%2,%3};"            \
        : "+f"(d[0]), "+f"(d[1]), "+f"(d[2]), "+f"(d[3])                   \
        : "r"(a[0]), "r"(a[1]), "r"(a[2]), "r"(a[3]), "r"(b[0]), "r"(b[1]))

// ---------------------------------------------------------------------------
// pack-all: x + 4 weights -> fp16, one launch
// ---------------------------------------------------------------------------
#define NX4 ((long)MDIM * CD / 4)
#define NW4 ((long)CD * CD / 4)

__global__ __launch_bounds__(256) void pack_all(
    const float* __restrict__ x,  const float* __restrict__ Wk,
    const float* __restrict__ Wv, const float* __restrict__ Wr,
    const float* __restrict__ Wo,
    __half* __restrict__ xp, __half* __restrict__ wkvr, __half* __restrict__ wop)
{
    long i = (long)blockIdx.x * blockDim.x + threadIdx.x;
    const float* src;
    __half* dst;
    long j;
    if (i < NX4) {
        src = x; dst = xp; j = i;
    } else {
        long i2 = i - NX4;
        int  w  = (int)(i2 / NW4);
        j = i2 - (long)w * NW4;
        if      (w == 0) { src = Wk; dst = wkvr; }
        else if (w == 1) { src = Wv; dst = wkvr + (size_t)CD * CD; }
        else if (w == 2) { src = Wr; dst = wkvr + (size_t)2 * CD * CD; }
        else             { src = Wo; dst = wop; }
    }
    float4 f = ((const float4*)src)[j];
    __half2* d = (__half2*)dst + 2 * j;
    d[0] = __floats2half2_rn(f.x, f.y);
    d[1] = __floats2half2_rn(f.z, f.w);
}

// ---------------------------------------------------------------------------
// FP16 tensor GEMM (R6 schedule, 4-stage pipeline): C = A[M,K] @ B[N,K]^T.
// Block 128x128x32, 256 thr = 8 warps (2M x 4N). One __syncthreads per iter;
// per-ks interleaved LDSM; prefetch after compute; distance-3 prefetch.
// ---------------------------------------------------------------------------
#define LDH 40
#define BUFB (128 * LDH * 2)
#define NSTAGE 4
#define SMEM_GEMM (NSTAGE * 2 * BUFB)   // 81920 B

__global__ __launch_bounds__(256, 2) void gemm_nt_h(
    const __half* __restrict__ A, const __half* __restrict__ B,
    float* __restrict__ C0, float* __restrict__ C1, float* __restrict__ C2,
    int K, int nsplit)
{
    extern __shared__ __align__(16) char dyn_smem[];
    const uint32_t sA = smem_u32(dyn_smem);
    const uint32_t sB = sA + NSTAGE * BUFB;

    const int tid  = threadIdx.x;
    const int lane = tid & 31;
    const int wid  = tid >> 5;
    const int wm   = (wid & 1) * 64;
    const int wn   = (wid >> 1) * 32;
    const int g    = lane >> 2;
    const int t4   = lane & 3;

    const int lr = tid >> 2;
    const int lu = tid & 3;
    const __half* Ap0 = A + (size_t)(blockIdx.y * 128 + lr) * K + lu * 8;
    const __half* Ap1 = Ap0 + (size_t)64 * K;
    const __half* Bp0 = B + (size_t)(blockIdx.x * 128 + lr) * K + lu * 8;
    const __half* Bp1 = Bp0 + (size_t)64 * K;
    const uint32_t da0 = sA + lr * 80 + lu * 16, da1 = da0 + 64 * 80;
    const uint32_t db0 = sB + lr * 80 + lu * 16, db1 = db0 + 64 * 80;

    const uint32_t a_base = sA + ((wm + (lane & 15)) * LDH + ((lane >> 4) << 3)) * 2;
    const uint32_t b_base = sB + ((wn + (lane & 7) + ((lane >> 4) & 1) * 8) * LDH
                                  + (((lane >> 3) & 1) << 3)) * 2;

    float acc[4][4][4];
#pragma unroll
    for (int mi = 0; mi < 4; mi++)
#pragma unroll
        for (int ni = 0; ni < 4; ni++)
#pragma unroll
            for (int j = 0; j < 4; j++) acc[mi][ni][j] = 0.f;

    const int KT = K / 32;   // 64

    // prologue: prefetch tiles 0..2
#pragma unroll
    for (int pf = 0; pf < NSTAGE - 1; pf++) {
        const uint32_t o = (uint32_t)(pf * BUFB);
        const int koff = pf * 32;
        cp16(da0 + o, Ap0 + koff); cp16(da1 + o, Ap1 + koff);
        cp16(db0 + o, Bp0 + koff); cp16(db1 + o, Bp1 + koff);
        CP_COMMIT();
    }

    int st = 0;
    for (int kt = 0; kt < KT; kt++) {
        // groups in flight at entry = min(KT - kt, 3); need tile kt done
        if (kt + 3 < KT)      { CP_WAIT(2); }
        else if (kt + 2 < KT) { CP_WAIT(1); }
        else                  { CP_WAIT(0); }
        __syncthreads();

        const uint32_t so = (uint32_t)(st * BUFB);
#pragma unroll
        for (int ks = 0; ks < 2; ks++) {
            const uint32_t ko = ks * 32;
            uint32_t af[4][4];
            uint32_t bf[4][2];
#pragma unroll
            for (int mi = 0; mi < 4; mi++)
                LDSM4(af[mi][0], af[mi][1], af[mi][2], af[mi][3],
                      a_base + so + mi * (16 * 80) + ko);
#pragma unroll
            for (int pr = 0; pr < 2; pr++)
                LDSM4(bf[2 * pr][0], bf[2 * pr][1], bf[2 * pr + 1][0], bf[2 * pr + 1][1],
                      b_base + so + pr * (16 * 80) + ko);
#pragma unroll
            for (int mi = 0; mi < 4; mi++)
#pragma unroll
                for (int ni = 0; ni < 4; ni++)
                    MMA_F16(acc[mi][ni], af[mi], bf[ni]);
        }

        if (kt + 3 < KT) {
            int ns = st + 3; if (ns >= NSTAGE) ns -= NSTAGE;
            const uint32_t o = (uint32_t)(ns * BUFB);
            const int koff = (kt + 3) * 32;
            cp16(da0 + o, Ap0 + koff); cp16(da1 + o, Ap1 + koff);
            cp16(db0 + o, Bp0 + koff); cp16(db1 + o, Bp1 + koff);
            CP_COMMIT();
        }
        if (++st == NSTAGE) st = 0;
    }

    float* C = C0;
    int cbx = blockIdx.x;
    if (nsplit > 0) {
        const int which = blockIdx.x / nsplit;
        C = (which == 0) ? C0 : ((which == 1) ? C1 : C2);
        cbx = blockIdx.x - which * nsplit;
    }
#pragma unroll
    for (int mi = 0; mi < 4; mi++) {
#pragma unroll
        for (int ni = 0; ni < 4; ni++) {
            const int row = blockIdx.y * 128 + wm + mi * 16 + g;
            const int col = cbx * 128 + wn + ni * 8 + 2 * t4;
            *(float2*)&C[(size_t)row * CD + col] =
                make_float2(acc[mi][ni][0], acc[mi][ni][1]);
            *(float2*)&C[(size_t)(row + 8) * CD + col] =
                make_float2(acc[mi][ni][2], acc[mi][ni][3]);
        }
    }
}

// ---------------------------------------------------------------------------
// WKV chunk-parallel scan (R6-proven scalar form, AoS float2 state).
// ---------------------------------------------------------------------------
__global__ __launch_bounds__(128) void wkv_p1(
    const float* __restrict__ k, const float* __restrict__ v,
    const float* __restrict__ td, const float* __restrict__ tf)
{
    const int s = threadIdx.x, p = blockIdx.x, h = blockIdx.y, b = blockIdx.z;
    const float decay = expf(-expf(td[h * SSZ + s]));
    const float first = expf(tf[h * SSZ + s]);
    size_t base = ((size_t)(b * TTL + p * LCH)) * CD + h * SSZ + s;
    float num = 0.f, den = 0.f;
#pragma unroll 4
    for (int i = 0; i < LCH; i++) {
        float kk = fminf(fmaxf(k[base], -10.f), 10.f);
        float w  = __expf(kk);
        if (p == 0 && i == 0) w *= first;
        num = fmaf(decay, num, w * v[base]);
        den = fmaf(decay, den, w);
        base += CD;
    }
    g_st[(((size_t)b * HH + h) * PCH + p) * SSZ + s] = make_float2(num, den);
}

__global__ __launch_bounds__(128) void wkv_p2(const float* __restrict__ td)
{
    const int s = threadIdx.x, h = blockIdx.x, b = blockIdx.y;
    const float dC = expf(-(float)LCH * expf(td[h * SSZ + s]));
    float2 run = make_float2(0.f, 0.f);
    size_t base = ((size_t)b * HH + h) * PCH;
    for (int p = 0; p < PCH; p++) {
        size_t idx = (base + p) * SSZ + s;
        float2 cur = g_st[idx];
        g_st[idx]  = run;
        run.x = fmaf(dC, run.x, cur.x);
        run.y = fmaf(dC, run.y, cur.y);
    }
}

__global__ __launch_bounds__(128) void wkv_p3(
    const float* __restrict__ k, const float* __restrict__ v,
    const float* __restrict__ r,
    const float* __restrict__ td, const float* __restrict__ tf)
{
    const int s = threadIdx.x, p = blockIdx.x, h = blockIdx.y, b = blockIdx.z;
    const float decay = expf(-expf(td[h * SSZ + s]));
    const float first = expf(tf[h * SSZ + s]);
    float2 st = g_st[(((size_t)b * HH + h) * PCH + p) * SSZ + s];
    float num = st.x, den = st.y;
    size_t base = ((size_t)(b * TTL + p * LCH)) * CD + h * SSZ + s;
#pragma unroll 4
    for (int i = 0; i < LCH; i++) {
        float kk = fminf(fmaxf(k[base], -10.f), 10.f);
        float w  = __expf(kk);
        if (p == 0 && i == 0) w *= first;
        num = fmaf(decay, num, w * v[base]);
        den = fmaf(decay, den, w);
        float rr  = r[base];
        float sig = 1.f / (1.f + __expf(-rr));
        g_gp[base] = __float2half_rn(sig * (num / (den + 1e-6f)));
        base += CD;
    }
}

// ---------------------------------------------------------------------------
extern "C" void kernel_launch(void* const* d_in, const int* in_sizes, int n_in,
                              void* d_out, int out_size)
{
    const float* x  = (const float*)d_in[0];
    const float* Wk = (const float*)d_in[1];
    const float* Wv = (const float*)d_in[2];
    const float* Wr = (const float*)d_in[3];
    const float* Wo = (const float*)d_in[4];
    const float* td = (const float*)d_in[5];
    const float* tf = (const float*)d_in[6];
    float* out = (float*)d_out;

    __half *xp, *wkvr, *wop, *gp;
    float *pk, *pv, *pr;
    cudaGetSymbolAddress((void**)&xp,   g_xp);
    cudaGetSymbolAddress((void**)&wkvr, g_wkvr);
    cudaGetSymbolAddress((void**)&wop,  g_wop);
    cudaGetSymbolAddress((void**)&gp,   g_gp);
    cudaGetSymbolAddress((void**)&pk,   g_k);
    cudaGetSymbolAddress((void**)&pv,   g_v);
    cudaGetSymbolAddress((void**)&pr,   g_r);

    cudaFuncSetAttribute(gemm_nt_h, cudaFuncAttributeMaxDynamicSharedMemorySize,
                         SMEM_GEMM);

    const long nAll = NX4 + 4 * NW4;
    pack_all<<<(unsigned)((nAll + 255) / 256), 256>>>(
        x, Wk, Wv, Wr, Wo, xp, wkvr, wop);

    dim3 gridF(3 * CD / 128, MDIM / 128);   // (48, 64)
    gemm_nt_h<<<gridF, 256, SMEM_GEMM>>>(xp, wkvr, pk, pv, pr, CD, CD / 128);

    wkv_p1<<<dim3(PCH, HH, 4), 128>>>(pk, pv, td, tf);
    wkv_p2<<<dim3(HH, 4), 128>>>(td);
    wkv_p3<<<dim3(PCH, HH, 4), 128>>>(pk, pv, pr, td, tf);

    dim3 gridO(CD / 128, MDIM / 128);       // (16, 64)
    gemm_nt_h<<<gridO, 256, SMEM_GEMM>>>(gp, wop, out, nullptr, nullptr, CD, 0);
}